// round 5
// baseline (speedup 1.0000x reference)
#include <cuda_runtime.h>

#define NTOK 512
#define DSTATE 192
#define HID 512
#define EMB 1024
#define NEMB 32
#define KC 256
#define CHT 24   // tokens per stage2 chunk
#define HSS 28   // smem row stride (floats): 112 B rows, 16B-aligned

// scratch (allocs forbidden -> device globals)
__device__ int g_start[NEMB + 1];
__device__ int g_tokens[NTOK];
__device__ float g_H[NTOK * 4 * HID]; // [slot][m][HID], grouped slot order

struct Params {
    const float* W1[4];
    const float* b1[4];
    const float* W2[4];
    const float* b2[4];
    const float* te[4];
};

// ---------------------------------------------------------------------------
// Stage 1 (fused grouping): each block re-derives the token grouping from the
// raw ids (deterministic rank-scan so every block agrees), block 0 publishes
// it for stage 2, then computes H[slot][m][:] = relu(x_m . W1_m[e] + b1_m[e]).
// Grid: 256 blocks = (jhalf, e, m), 256 threads = one HID column each.
// ---------------------------------------------------------------------------
template <int L, int OFF>
__device__ __forceinline__ void mlp1(const float* __restrict__ state,
                                     const float* __restrict__ W1,
                                     float b, int m, int j, int s0, int n,
                                     const int* __restrict__ s_tokens,
                                     float* __restrict__ xs) {
    int tid = threadIdx.x;
    for (int cb = 0; cb < n; cb += 16) {
        int rem = min(n - cb, 16);
        __syncthreads();
        for (int idx = tid; idx < 16 * L; idx += 256) {
            int tk = idx / L, l = idx % L;
            float v = 0.f;
            if (tk < rem) {
                int tok = s_tokens[s0 + cb + tk];
                v = state[tok * DSTATE + OFF + l];
            }
            xs[tk * L + l] = v;
        }
        __syncthreads();

        float acc[16];
        #pragma unroll
        for (int t = 0; t < 16; t++) acc[t] = b;

        #pragma unroll 1
        for (int l0 = 0; l0 < L; l0 += 8) {
            float w[8];
            #pragma unroll
            for (int u = 0; u < 8; u++)
                w[u] = W1[(l0 + u) * HID + j];
            #pragma unroll
            for (int u = 0; u < 8; u++) {
                #pragma unroll
                for (int t = 0; t < 16; t++)
                    acc[t] = fmaf(xs[t * L + l0 + u], w[u], acc[t]);
            }
        }

        #pragma unroll
        for (int t = 0; t < 16; t++) {
            if (t < rem)
                g_H[((size_t)(s0 + cb + t) * 4 + m) * HID + j] = fmaxf(acc[t], 0.f);
        }
        __syncthreads();
    }
}

__global__ void __launch_bounds__(256) k_stage1(const float* __restrict__ state,
                                                const int* __restrict__ ids_raw,
                                                Params p) {
    __shared__ int s_cnt[NEMB];
    __shared__ int s_startA[NEMB + 1];
    __shared__ int s_ids[NTOK];
    __shared__ int s_tokens[NTOK];
    __shared__ int s_i64;
    __shared__ float xs[16 * 64];

    int tid = threadIdx.x; // 256

    if (tid < NEMB) s_cnt[tid] = 0;
    if (tid == 0) s_i64 = 1;
    __syncthreads();
    // int64 ids (<32) have zero high words at odd int32 indices. Index 2t+1
    // stays within 512 words, safe for int32 buffers too.
    if (ids_raw[2 * tid + 1] != 0) s_i64 = 0;
    __syncthreads();

    int t0 = tid, t1 = tid + 256;
    int c0 = s_i64 ? ids_raw[2 * t0] : ids_raw[t0];
    int c1 = s_i64 ? ids_raw[2 * t1] : ids_raw[t1];
    s_ids[t0] = c0;
    s_ids[t1] = c1;
    atomicAdd(&s_cnt[c0], 1);
    atomicAdd(&s_cnt[c1], 1);
    __syncthreads();

    if (tid <= NEMB) {
        int s = 0;
        for (int jj = 0; jj < tid && jj < NEMB; jj++) s += s_cnt[jj];
        s_startA[tid] = s;
    }
    __syncthreads();

    // deterministic scatter: rank = #earlier tokens with same id
    int r0 = 0, r1 = 0;
    for (int t = 0; t < NTOK; t++) {
        int cc = s_ids[t];
        r0 += (t < t0 && cc == c0);
        r1 += (t < t1 && cc == c1);
    }
    __syncthreads();
    s_tokens[s_startA[c0] + r0] = t0;
    s_tokens[s_startA[c1] + r1] = t1;
    __syncthreads();

    if (blockIdx.x == 0) {
        if (tid <= NEMB) g_start[tid] = s_startA[tid];
        g_tokens[t0] = s_tokens[t0];
        g_tokens[t1] = s_tokens[t1];
    }

    // ---- per-block MLP: bx = (jh<<7) | (e<<2) | m
    int bx = blockIdx.x;
    int m  = bx & 3;
    int e  = (bx >> 2) & 31;
    int jh = bx >> 7;
    int j  = jh * 256 + tid;

    int s0 = s_startA[e];
    int n  = s_startA[e + 1] - s0;
    if (n == 0) return;

    float b;
    switch (m) {
        case 0: b = p.b1[0][e * HID + j];
                mlp1<64, 0  >(state, p.W1[0] + (size_t)e * 64 * HID, b, 0, j, s0, n, s_tokens, xs); break;
        case 1: b = p.b1[1][e * HID + j];
                mlp1<64, 64 >(state, p.W1[1] + (size_t)e * 64 * HID, b, 1, j, s0, n, s_tokens, xs); break;
        case 2: b = p.b1[2][e * HID + j];
                mlp1<32, 128>(state, p.W1[2] + (size_t)e * 32 * HID, b, 2, j, s0, n, s_tokens, xs); break;
        case 3: b = p.b1[3][e * HID + j];
                mlp1<32, 160>(state, p.W1[3] + (size_t)e * 32 * HID, b, 3, j, s0, n, s_tokens, xs); break;
    }
}

// ---------------------------------------------------------------------------
// Kernel 2: out = H . W2[e] + b2[e] + te.
// Block = (256-col tile, m, e); thread owns 2 adjacent columns (LDG.64 W2).
// Chunk = 24 tokens; h via broadcast LDS.128 shared across both columns.
// ---------------------------------------------------------------------------
__device__ __forceinline__ void fma2(unsigned long long& acc,
                                     unsigned long long h2,
                                     unsigned long long w2) {
    asm("fma.rn.f32x2 %0, %1, %2, %0;" : "+l"(acc) : "l"(h2), "l"(w2));
}

template <int P>  // P even, 2..12: token pairs in flight
__device__ __forceinline__ void run_chunk(
    float* hs, const float* __restrict__ W2ec, const float* __restrict__ Hme,
    float2 init, int s0cb, int rem, int tid, int m, int c0,
    float* __restrict__ out)
{
    constexpr int D = 8;  // W2 prefetch depth (LDG.64 -> 16 lines/warp in flight)

    unsigned long long a0[P], a1[P];
    unsigned long long i0, i1;
    asm("mov.b64 %0, {%1,%1};" : "=l"(i0) : "r"(__float_as_uint(init.x)));
    asm("mov.b64 %0, {%1,%1};" : "=l"(i1) : "r"(__float_as_uint(init.y)));
    #pragma unroll
    for (int p = 0; p < P; p++) { a0[p] = i0; a1[p] = i1; }

    for (int kc = 0; kc < HID; kc += KC) {
        __syncthreads();
        // stage h transposed: hs[kk*HSS + tk], tk in [0, 2P)
        #pragma unroll
        for (int tk = 0; tk < 2 * P; tk++) {
            int slot = min(s0cb + tk, NTOK - 1); // clamp pad (discarded later)
            const float* src = Hme + (size_t)slot * (4 * HID) + kc;
            #pragma unroll
            for (int kk = 0; kk < KC; kk += 128)
                hs[(kk + tid) * HSS + tk] = src[kk + tid];
        }
        __syncthreads();

        const float* wp = W2ec + (size_t)kc * EMB;
        #pragma unroll 1
        for (int g = 0; g < KC; g += D) {
            // front-batch D independent streaming LDG.64 -> 2D lines in flight
            float2 w[D];
            #pragma unroll
            for (int j = 0; j < D; j++)
                w[j] = __ldcs((const float2*)(wp + (size_t)(g + j) * EMB));

            #pragma unroll
            for (int j = 0; j < D; j++) {
                unsigned long long w0, w1;
                asm("mov.b64 %0, {%1,%1};" : "=l"(w0) : "r"(__float_as_uint(w[j].x)));
                asm("mov.b64 %0, {%1,%1};" : "=l"(w1) : "r"(__float_as_uint(w[j].y)));
                const float* hrow = hs + (g + j) * HSS;
                #pragma unroll
                for (int p2 = 0; p2 < P / 2; p2++) {
                    ulonglong2 hv = *(const ulonglong2*)(hrow + 4 * p2); // LDS.128 bcast
                    fma2(a0[2 * p2],     hv.x, w0);
                    fma2(a0[2 * p2 + 1], hv.y, w0);
                    fma2(a1[2 * p2],     hv.x, w1);
                    fma2(a1[2 * p2 + 1], hv.y, w1);
                }
            }
        }
    }

    #pragma unroll
    for (int p = 0; p < P; p++) {
        float2 vA = *(float2*)&a0[p]; // col c0:   (tok 2p, tok 2p+1)
        float2 vB = *(float2*)&a1[p]; // col c0+1
        int t0 = 2 * p;
        if (t0 < rem) {
            int tok = g_tokens[s0cb + t0];
            *(float2*)&out[((size_t)tok * 4 + m) * EMB + c0] = make_float2(vA.x, vB.x);
        }
        if (t0 + 1 < rem) {
            int tok = g_tokens[s0cb + t0 + 1];
            *(float2*)&out[((size_t)tok * 4 + m) * EMB + c0] = make_float2(vA.y, vB.y);
        }
    }
}

__global__ void __launch_bounds__(128, 5) k_stage2(Params p, float* __restrict__ out) {
    int tile = blockIdx.x; // 0..3 (256 cols each)
    int m    = blockIdx.y; // 0..3
    int e    = blockIdx.z; // 0..31
    int s0 = g_start[e];
    int n  = g_start[e + 1] - s0;
    if (n == 0) return;

    int tid = threadIdx.x;
    int c0 = tile * 256 + tid * 2;
    const float* __restrict__ W2ec = p.W2[m] + (size_t)e * HID * EMB + c0;
    const float* __restrict__ Hme  = g_H + m * HID;
    float2 init = make_float2(p.b2[m][e * EMB + c0]     + p.te[m][c0],
                              p.b2[m][e * EMB + c0 + 1] + p.te[m][c0 + 1]);

    __shared__ __align__(16) float hs[KC * HSS];

    for (int cb = 0; cb < n; cb += CHT) {
        int rem = min(n - cb, CHT);
        int pairsEven = ((rem + 3) >> 2) << 1; // even ceil(rem/2)
        int s0cb = s0 + cb;
        switch (pairsEven) {
#define CASE(PP) case PP: run_chunk<PP>(hs, W2ec, Hme, init, s0cb, rem, tid, m, c0, out); break;
            CASE(2) CASE(4) CASE(6) CASE(8) CASE(10) CASE(12)
#undef CASE
        }
    }
}

// ---------------------------------------------------------------------------
extern "C" void kernel_launch(void* const* d_in, const int* in_sizes, int n_in,
                              void* d_out, int out_size) {
    const float* state = (const float*)d_in[0];
    const int*   ids   = (const int*)d_in[1];

    Params P;
    int base = 2;
    for (int m = 0; m < 4; m++) {
        P.W1[m] = (const float*)d_in[base + 0];
        P.b1[m] = (const float*)d_in[base + 1];
        P.W2[m] = (const float*)d_in[base + 2];
        P.b2[m] = (const float*)d_in[base + 3];
        P.te[m] = (const float*)d_in[base + 4];
        base += 5;
    }
    float* out = (float*)d_out;

    k_stage1<<<256, 256>>>(state, ids, P);
    k_stage2<<<dim3(4, 4, 32), 128>>>(P, out);
}

// round 6
// speedup vs baseline: 1.4094x; 1.4094x over previous
#include <cuda_runtime.h>

#define NTOK 512
#define DSTATE 192
#define HID 512
#define EMB 1024
#define NEMB 32
#define KC 256
#define CHT 24   // tokens per stage2 chunk
#define HSS 28   // smem row stride (floats): 112 B rows, 16B-aligned

// scratch (allocs forbidden -> device globals)
__device__ int g_start[NEMB + 1];
__device__ int g_tokens[NTOK];
__device__ float g_H[NTOK * 4 * HID]; // [slot][m][HID], grouped slot order

struct Params {
    const float* W1[4];
    const float* b1[4];
    const float* W2[4];
    const float* b2[4];
    const float* te[4];
};

// ---------------------------------------------------------------------------
// Stage 1 (fused grouping): each block re-derives the token grouping from the
// raw ids (deterministic rank-scan so every block agrees), block 0 publishes
// it for stage 2, then computes H[slot][m][:] = relu(x_m . W1_m[e] + b1_m[e]).
// Grid: 128 blocks = (e,m), 512 threads = one HID column each.
// ---------------------------------------------------------------------------
template <int L, int OFF>
__device__ __forceinline__ void mlp1(const float* __restrict__ state,
                                     const float* __restrict__ W1,
                                     float b, int m, int s0, int n,
                                     const int* __restrict__ s_tokens,
                                     float* __restrict__ xs) {
    int j = threadIdx.x;
    for (int cb = 0; cb < n; cb += 16) {
        int rem = min(n - cb, 16);
        __syncthreads();
        for (int idx = j; idx < 16 * L; idx += 512) {
            int tk = idx / L, l = idx % L;
            float v = 0.f;
            if (tk < rem) {
                int tok = s_tokens[s0 + cb + tk];
                v = state[tok * DSTATE + OFF + l];
            }
            xs[tk * L + l] = v;
        }
        __syncthreads();

        float acc[16];
        #pragma unroll
        for (int t = 0; t < 16; t++) acc[t] = b;

        #pragma unroll 1
        for (int l0 = 0; l0 < L; l0 += 8) {
            float w[8];
            #pragma unroll
            for (int u = 0; u < 8; u++)
                w[u] = W1[(l0 + u) * HID + j];
            #pragma unroll
            for (int u = 0; u < 8; u++) {
                #pragma unroll
                for (int t = 0; t < 16; t++)
                    acc[t] = fmaf(xs[t * L + l0 + u], w[u], acc[t]);
            }
        }

        #pragma unroll
        for (int t = 0; t < 16; t++) {
            if (t < rem)
                g_H[((size_t)(s0 + cb + t) * 4 + m) * HID + j] = fmaxf(acc[t], 0.f);
        }
        __syncthreads();
    }
}

__global__ void __launch_bounds__(512) k_stage1(const float* __restrict__ state,
                                                const int* __restrict__ ids_raw,
                                                Params p) {
    __shared__ int s_cnt[NEMB];
    __shared__ int s_startA[NEMB + 1];
    __shared__ int s_tokens[NTOK];
    __shared__ int s_i64;
    __shared__ float xs[16 * 64];

    int tid = threadIdx.x; // 512

    if (tid < NEMB) s_cnt[tid] = 0;
    if (tid == 0) s_i64 = 1;
    __syncthreads();
    if (tid < 256 && ids_raw[2 * tid + 1] != 0) s_i64 = 0;
    __syncthreads();
    int myc = s_i64 ? ids_raw[2 * tid] : ids_raw[tid];
    atomicAdd(&s_cnt[myc], 1);
    __syncthreads();
    if (tid <= NEMB) {
        int s = 0;
        for (int jj = 0; jj < tid && jj < NEMB; jj++) s += s_cnt[jj];
        s_startA[tid] = s;
    }
    __syncthreads();
    // deterministic scatter: rank = #earlier tokens with same id (stable).
    s_tokens[tid] = myc;
    __syncthreads();
    int rank = 0;
    for (int t = 0; t < NTOK; t++) {
        int c2 = s_tokens[t];
        if (t < tid && c2 == myc) rank++;
    }
    __syncthreads();
    int slot = s_startA[myc] + rank;
    s_tokens[slot] = tid;
    __syncthreads();

    if (blockIdx.x == 0) {
        if (tid <= NEMB) g_start[tid] = s_startA[tid];
        g_tokens[tid] = s_tokens[tid];
    }

    // ---- per-block MLP
    int m = blockIdx.x & 3;
    int e = blockIdx.x >> 2;
    int s0 = s_startA[e];
    int n  = s_startA[e + 1] - s0;
    if (n == 0) return;

    float b;
    switch (m) {
        case 0: b = p.b1[0][e * HID + tid];
                mlp1<64, 0  >(state, p.W1[0] + (size_t)e * 64 * HID, b, 0, s0, n, s_tokens, xs); break;
        case 1: b = p.b1[1][e * HID + tid];
                mlp1<64, 64 >(state, p.W1[1] + (size_t)e * 64 * HID, b, 1, s0, n, s_tokens, xs); break;
        case 2: b = p.b1[2][e * HID + tid];
                mlp1<32, 128>(state, p.W1[2] + (size_t)e * 32 * HID, b, 2, s0, n, s_tokens, xs); break;
        case 3: b = p.b1[3][e * HID + tid];
                mlp1<32, 160>(state, p.W1[3] + (size_t)e * 32 * HID, b, 3, s0, n, s_tokens, xs); break;
    }
}

// ---------------------------------------------------------------------------
// Kernel 2: out = H . W2[e] + b2[e] + te.
// Block = (256-col tile, m, e); thread owns 2 adjacent columns (LDG.64 W2).
// W2 stream is SOFTWARE-PIPELINED (double-buffered register groups of D=8
// LDG.64) so ~16 lines/warp stay in flight continuously.
// ---------------------------------------------------------------------------
__device__ __forceinline__ void fma2(unsigned long long& acc,
                                     unsigned long long h2,
                                     unsigned long long w2) {
    asm("fma.rn.f32x2 %0, %1, %2, %0;" : "+l"(acc) : "l"(h2), "l"(w2));
}

#define WD 8  // W2 prefetch group size (LDG.64 each -> 16 lines/warp)

template <int P>
__device__ __forceinline__ void consume(const float2* w, const float* hs, int g,
                                        unsigned long long* a0, unsigned long long* a1) {
    #pragma unroll
    for (int j = 0; j < WD; j++) {
        unsigned long long w0, w1;
        asm("mov.b64 %0, {%1,%1};" : "=l"(w0) : "r"(__float_as_uint(w[j].x)));
        asm("mov.b64 %0, {%1,%1};" : "=l"(w1) : "r"(__float_as_uint(w[j].y)));
        const float* hrow = hs + (g + j) * HSS;
        #pragma unroll
        for (int p2 = 0; p2 < P / 2; p2++) {
            ulonglong2 hv = *(const ulonglong2*)(hrow + 4 * p2); // LDS.128 bcast
            fma2(a0[2 * p2],     hv.x, w0);
            fma2(a0[2 * p2 + 1], hv.y, w0);
            fma2(a1[2 * p2],     hv.x, w1);
            fma2(a1[2 * p2 + 1], hv.y, w1);
        }
    }
}

template <int P>  // P even, 2..12: token pairs in flight
__device__ __forceinline__ void run_chunk(
    float* hs, const float* __restrict__ W2ec, const float* __restrict__ Hme,
    float2 init, int s0cb, int rem, int tid, int m, int c0,
    float* __restrict__ out)
{
    unsigned long long a0[P], a1[P];
    unsigned long long i0, i1;
    asm("mov.b64 %0, {%1,%1};" : "=l"(i0) : "r"(__float_as_uint(init.x)));
    asm("mov.b64 %0, {%1,%1};" : "=l"(i1) : "r"(__float_as_uint(init.y)));
    #pragma unroll
    for (int p = 0; p < P; p++) { a0[p] = i0; a1[p] = i1; }

    for (int kc = 0; kc < HID; kc += KC) {
        __syncthreads();
        // stage h transposed: hs[kk*HSS + tk], tk in [0, 2P)
        #pragma unroll
        for (int tk = 0; tk < 2 * P; tk++) {
            int slot = min(s0cb + tk, NTOK - 1); // clamp pad (discarded later)
            const float* src = Hme + (size_t)slot * (4 * HID) + kc;
            #pragma unroll
            for (int kk = 0; kk < KC; kk += 128)
                hs[(kk + tid) * HSS + tk] = src[kk + tid];
        }
        __syncthreads();

        const float* wp = W2ec + (size_t)kc * EMB;
        float2 wA[WD], wB[WD];

        #pragma unroll
        for (int j = 0; j < WD; j++)
            wA[j] = __ldcs((const float2*)(wp + (size_t)j * EMB));

        #pragma unroll 1
        for (int g = 0; g < KC - 2 * WD; g += 2 * WD) {
            #pragma unroll
            for (int j = 0; j < WD; j++)
                wB[j] = __ldcs((const float2*)(wp + (size_t)(g + WD + j) * EMB));
            consume<P>(wA, hs, g, a0, a1);
            #pragma unroll
            for (int j = 0; j < WD; j++)
                wA[j] = __ldcs((const float2*)(wp + (size_t)(g + 2 * WD + j) * EMB));
            consume<P>(wB, hs, g + WD, a0, a1);
        }
        // tail: groups KC-2*WD and KC-WD
        #pragma unroll
        for (int j = 0; j < WD; j++)
            wB[j] = __ldcs((const float2*)(wp + (size_t)(KC - WD + j) * EMB));
        consume<P>(wA, hs, KC - 2 * WD, a0, a1);
        consume<P>(wB, hs, KC - WD, a0, a1);
    }

    #pragma unroll
    for (int p = 0; p < P; p++) {
        float2 vA = *(float2*)&a0[p]; // col c0:   (tok 2p, tok 2p+1)
        float2 vB = *(float2*)&a1[p]; // col c0+1
        int t0 = 2 * p;
        if (t0 < rem) {
            int tok = g_tokens[s0cb + t0];
            *(float2*)&out[((size_t)tok * 4 + m) * EMB + c0] = make_float2(vA.x, vB.x);
        }
        if (t0 + 1 < rem) {
            int tok = g_tokens[s0cb + t0 + 1];
            *(float2*)&out[((size_t)tok * 4 + m) * EMB + c0] = make_float2(vA.y, vB.y);
        }
    }
}

__global__ void __launch_bounds__(128, 4) k_stage2(Params p, float* __restrict__ out) {
    int tile = blockIdx.x; // 0..3 (256 cols each)
    int m    = blockIdx.y; // 0..3
    int e    = blockIdx.z; // 0..31
    int s0 = g_start[e];
    int n  = g_start[e + 1] - s0;
    if (n == 0) return;

    int tid = threadIdx.x;
    int c0 = tile * 256 + tid * 2;
    const float* __restrict__ W2ec = p.W2[m] + (size_t)e * HID * EMB + c0;
    const float* __restrict__ Hme  = g_H + m * HID;
    float2 init = make_float2(p.b2[m][e * EMB + c0]     + p.te[m][c0],
                              p.b2[m][e * EMB + c0 + 1] + p.te[m][c0 + 1]);

    __shared__ __align__(16) float hs[KC * HSS];

    for (int cb = 0; cb < n; cb += CHT) {
        int rem = min(n - cb, CHT);
        int pairsEven = ((rem + 3) >> 2) << 1; // even ceil(rem/2)
        int s0cb = s0 + cb;
        switch (pairsEven) {
#define CASE(PP) case PP: run_chunk<PP>(hs, W2ec, Hme, init, s0cb, rem, tid, m, c0, out); break;
            CASE(2) CASE(4) CASE(6) CASE(8) CASE(10) CASE(12)
#undef CASE
        }
    }
}

// ---------------------------------------------------------------------------
extern "C" void kernel_launch(void* const* d_in, const int* in_sizes, int n_in,
                              void* d_out, int out_size) {
    const float* state = (const float*)d_in[0];
    const int*   ids   = (const int*)d_in[1];

    Params P;
    int base = 2;
    for (int m = 0; m < 4; m++) {
        P.W1[m] = (const float*)d_in[base + 0];
        P.b1[m] = (const float*)d_in[base + 1];
        P.W2[m] = (const float*)d_in[base + 2];
        P.b2[m] = (const float*)d_in[base + 3];
        P.te[m] = (const float*)d_in[base + 4];
        base += 5;
    }
    float* out = (float*)d_out;

    k_stage1<<<128, 512>>>(state, ids, P);
    k_stage2<<<dim3(4, 4, 32), 128>>>(P, out);
}